// round 3
// baseline (speedup 1.0000x reference)
#include <cuda_runtime.h>
#include <cstdint>

// Problem constants (fixed shape (8,2048,2048) fp32, ratio 0.1)
#define N_ELEMS   33554432
#define N_VEC4    (N_ELEMS / 4)
#define K_TOP     3355443           // int(0.1 * N)
#define SBINS     8192              // sample histogram bins (13 bits of 31-bit key)
#define SSHIFT    18                // 31-bit key >> 18 -> 13-bit bin
#define WIN_BINS  (1 << 20)         // exact window: 4 coarse bins * 2^18 keys
#define WCHUNK    1024
#define NCHUNKS   (WIN_BINS / WCHUNK)
#define EQ_CAP    65536
#define LIST_CAP  (1 << 23)         // 8M entries, ~10x expected window population
#define STAGE_CAP 2048              // per-block staging (mean 726, 49 sigma margin)
#define SAMPLE_V4 262144            // 1/32 of float4s sampled
#define STARGET   (K_TOP / 32)

#define GRID_MAIN 1184
#define BLK_MAIN  256

__device__ unsigned int g_shist[SBINS];
__device__ unsigned int g_winHist[WIN_BINS];
__device__ unsigned int g_chunkSum[NCHUNKS];
__device__ unsigned int g_above;
__device__ unsigned int g_lo;
__device__ unsigned int g_T;
__device__ unsigned int g_need;
__device__ unsigned int g_nList;
__device__ uint2        g_list[LIST_CAP];
__device__ unsigned int g_eqCount;
__device__ unsigned int g_eqIdx[EQ_CAP];
__device__ unsigned int g_eqVal[EQ_CAP];

// ---------------------------------------------------------------------------
__global__ void k_zero() {
    int tid = blockIdx.x * blockDim.x + threadIdx.x;
    int stride = gridDim.x * blockDim.x;
    for (int i = tid; i < WIN_BINS; i += stride) g_winHist[i] = 0;
    for (int i = tid; i < SBINS; i += stride) g_shist[i] = 0;
    if (tid == 0) { g_above = 0; g_eqCount = 0; g_nList = 0; }
}

// ---------------------------------------------------------------------------
// Sample 1/32 of the data into a 13-bit shared histogram, flush to global.
__global__ void k_sample(const float4* __restrict__ x) {
    __shared__ unsigned int sh[SBINS];
    for (int i = threadIdx.x; i < SBINS; i += blockDim.x) sh[i] = 0;
    __syncthreads();

    int tid = blockIdx.x * blockDim.x + threadIdx.x;
    int stride = gridDim.x * blockDim.x;
    for (int i = tid; i < SAMPLE_V4; i += stride) {
        int p = ((i >> 6) << 11) + (i & 63);   // 64 f4 per 2048-f4 group
        float4 v = x[p];
        atomicAdd(&sh[(__float_as_uint(v.x) & 0x7FFFFFFFu) >> SSHIFT], 1u);
        atomicAdd(&sh[(__float_as_uint(v.y) & 0x7FFFFFFFu) >> SSHIFT], 1u);
        atomicAdd(&sh[(__float_as_uint(v.z) & 0x7FFFFFFFu) >> SSHIFT], 1u);
        atomicAdd(&sh[(__float_as_uint(v.w) & 0x7FFFFFFFu) >> SSHIFT], 1u);
    }
    __syncthreads();
    for (int i = threadIdx.x; i < SBINS; i += blockDim.x) {
        unsigned int c = sh[i];
        if (c) atomicAdd(&g_shist[i], c);
    }
}

// ---------------------------------------------------------------------------
// Locate the coarse bin of the estimated k-th value; open a 4-bin window.
__global__ void k_sscan() {
    __shared__ unsigned int suf[1024];
    int t = threadIdx.x;
    unsigned int s = 0;
#pragma unroll
    for (int j = 0; j < 8; j++) s += g_shist[t * 8 + j];
    suf[t] = s;
    __syncthreads();
    for (int d = 1; d < 1024; d <<= 1) {
        unsigned int v = (t + d < 1024) ? suf[t + d] : 0;
        __syncthreads();
        suf[t] += v;
        __syncthreads();
    }
    unsigned int segAbove = (t < 1023) ? suf[t + 1] : 0;
    if (suf[t] >= (unsigned)STARGET && segAbove < (unsigned)STARGET) {
        unsigned int acc = segAbove;
        int bin = t * 8;
        for (int j = 7; j >= 0; j--) {
            acc += g_shist[t * 8 + j];
            if (acc >= (unsigned)STARGET) { bin = t * 8 + j; break; }
        }
        int lo_bin = bin >= 2 ? bin - 2 : 0;
        if (lo_bin > SBINS - 4) lo_bin = SBINS - 4;
        g_lo = (unsigned)lo_bin << SSHIFT;
    }
}

// ---------------------------------------------------------------------------
// FUSED pass: read x, write provisional out (keep if b>=hi, else 0),
// count elements above the window, stage in-window (idx, rawbits) pairs in
// shared memory, flush per block with ONE global atomic.
struct MainSmem {
    unsigned int count;       // staged entries
    unsigned int above;       // block 'above' accumulator
    unsigned int base;        // global flush base
    uint2 stage[STAGE_CAP];
};

__device__ __forceinline__ void stage_put(MainSmem* sm, unsigned lane,
                                          bool put, unsigned idx, unsigned raw) {
    unsigned m = __ballot_sync(0xFFFFFFFFu, put);
    if (m) {
        int leader = __ffs(m) - 1;
        unsigned base;
        if ((int)lane == leader) base = atomicAdd(&sm->count, (unsigned)__popc(m));
        base = __shfl_sync(0xFFFFFFFFu, base, leader);
        if (put) {
            unsigned pos = base + __popc(m & ((1u << lane) - 1u));
            if (pos < STAGE_CAP) sm->stage[pos] = make_uint2(idx, raw);
        }
    }
}

__device__ __forceinline__ unsigned proc_vec(MainSmem* sm, unsigned lane,
                                             float4 v, unsigned i4,
                                             unsigned lo, unsigned hi,
                                             float4* __restrict__ out) {
    unsigned bx = __float_as_uint(v.x) & 0x7FFFFFFFu;
    unsigned by = __float_as_uint(v.y) & 0x7FFFFFFFu;
    unsigned bz = __float_as_uint(v.z) & 0x7FFFFFFFu;
    unsigned bw = __float_as_uint(v.w) & 0x7FFFFFFFu;
    float4 o;
    o.x = (bx >= hi) ? v.x : 0.0f;
    o.y = (by >= hi) ? v.y : 0.0f;
    o.z = (bz >= hi) ? v.z : 0.0f;
    o.w = (bw >= hi) ? v.w : 0.0f;
    out[i4] = o;
    unsigned cnt = (bx >= hi) + (by >= hi) + (bz >= hi) + (bw >= hi);
    // unsigned wrap trick: b<lo -> huge -> false
    stage_put(sm, lane, (bx - lo) < WIN_BINS, i4 * 4u + 0u, __float_as_uint(v.x));
    stage_put(sm, lane, (by - lo) < WIN_BINS, i4 * 4u + 1u, __float_as_uint(v.y));
    stage_put(sm, lane, (bz - lo) < WIN_BINS, i4 * 4u + 2u, __float_as_uint(v.z));
    stage_put(sm, lane, (bw - lo) < WIN_BINS, i4 * 4u + 3u, __float_as_uint(v.w));
    return cnt;
}

__global__ void __launch_bounds__(BLK_MAIN) k_main(const float4* __restrict__ x,
                                                   float4* __restrict__ out) {
    __shared__ MainSmem sm;
    if (threadIdx.x == 0) { sm.count = 0; sm.above = 0; }
    __syncthreads();

    const unsigned lo = g_lo;
    const unsigned hi = lo + WIN_BINS;
    const unsigned lane = threadIdx.x & 31u;
    unsigned above = 0;

    int tid = blockIdx.x * blockDim.x + threadIdx.x;
    const int stride = gridDim.x * blockDim.x;

    int i = tid;
    // unrolled x4: independent loads for MLP
    for (; i + 3 * stride < N_VEC4; i += 4 * stride) {
        float4 v0 = x[i];
        float4 v1 = x[i + stride];
        float4 v2 = x[i + 2 * stride];
        float4 v3 = x[i + 3 * stride];
        above += proc_vec(&sm, lane, v0, (unsigned)i, lo, hi, out);
        above += proc_vec(&sm, lane, v1, (unsigned)(i + stride), lo, hi, out);
        above += proc_vec(&sm, lane, v2, (unsigned)(i + 2 * stride), lo, hi, out);
        above += proc_vec(&sm, lane, v3, (unsigned)(i + 3 * stride), lo, hi, out);
    }
    for (; i < N_VEC4; i += stride) {
        float4 v = x[i];
        above += proc_vec(&sm, lane, v, (unsigned)i, lo, hi, out);
    }

    // reduce 'above' within warp, then block, then one RED per block
#pragma unroll
    for (int off = 16; off; off >>= 1) above += __shfl_down_sync(0xFFFFFFFFu, above, off);
    if (lane == 0 && above) atomicAdd(&sm.above, above);
    __syncthreads();

    // flush staged entries: one global atomic per block, coalesced copy
    if (threadIdx.x == 0) {
        if (sm.above) atomicAdd(&g_above, sm.above);
        unsigned n = sm.count < STAGE_CAP ? sm.count : STAGE_CAP;
        sm.base = atomicAdd(&g_nList, n);
        sm.count = n;
    }
    __syncthreads();
    unsigned n = sm.count, base = sm.base;
    for (unsigned j = threadIdx.x; j < n; j += blockDim.x) {
        unsigned pos = base + j;
        if (pos < LIST_CAP) g_list[pos] = sm.stage[j];
    }
}

// ---------------------------------------------------------------------------
// Build the exact window histogram from the compact list.
__global__ void k_hist() {
    unsigned n = g_nList; if (n > LIST_CAP) n = LIST_CAP;
    unsigned lo = g_lo;
    int tid = blockIdx.x * blockDim.x + threadIdx.x;
    int stride = gridDim.x * blockDim.x;
    for (unsigned j = tid; j < n; j += stride) {
        unsigned b = (g_list[j].y & 0x7FFFFFFFu) - lo;
        atomicAdd(&g_winHist[b], 1u);
    }
}

// ---------------------------------------------------------------------------
__global__ void k_wreduce() {
    __shared__ unsigned int smr[256];
    unsigned int s = 0;
    int base = blockIdx.x * WCHUNK;
    for (int j = threadIdx.x; j < WCHUNK; j += 256) s += g_winHist[base + j];
    smr[threadIdx.x] = s;
    __syncthreads();
    for (int off = 128; off; off >>= 1) {
        if (threadIdx.x < off) smr[threadIdx.x] += smr[threadIdx.x + off];
        __syncthreads();
    }
    if (threadIdx.x == 0) g_chunkSum[blockIdx.x] = smr[0];
}

// ---------------------------------------------------------------------------
// Exact threshold T (31-bit key of k-th largest) + tie budget.
__global__ void k_wscan() {
    __shared__ unsigned int suf[1024];
    __shared__ int s_c;
    int t = threadIdx.x;

    suf[t] = g_chunkSum[t];
    __syncthreads();
    for (int d = 1; d < 1024; d <<= 1) {
        unsigned int v = (t + d < 1024) ? suf[t + d] : 0;
        __syncthreads();
        suf[t] += v;
        __syncthreads();
    }
    unsigned int above = g_above;
    long long kRem = (long long)K_TOP - (long long)above;
    unsigned int winTotal = suf[0];

    if (kRem < 1) {                    // degenerate: window missed low
        if (t == 0) { g_T = g_lo + WIN_BINS - 1; g_need = 0; }
        return;
    }
    if (kRem > (long long)winTotal) {  // degenerate: window missed high
        if (t == 0) { g_T = g_lo > 0 ? g_lo - 1 : 0; g_need = 0; }
        return;
    }
    unsigned int segAbove = (t < 1023) ? suf[t + 1] : 0;
    if ((long long)suf[t] >= kRem && (long long)segAbove < kRem) s_c = t;
    __syncthreads();
    int c = s_c;
    unsigned int baseAbove = (c < 1023) ? suf[c + 1] : 0;
    __syncthreads();

    suf[t] = g_winHist[c * WCHUNK + t];
    __syncthreads();
    for (int d = 1; d < 1024; d <<= 1) {
        unsigned int v = (t + d < 1024) ? suf[t + d] : 0;
        __syncthreads();
        suf[t] += v;
        __syncthreads();
    }
    unsigned int binAbove = baseAbove + ((t < 1023) ? suf[t + 1] : 0);
    if ((long long)(baseAbove + suf[t]) >= kRem && (long long)binAbove < kRem) {
        unsigned int bin = (unsigned)c * WCHUNK + (unsigned)t;
        g_T = g_lo + bin;
        g_need = (unsigned)(kRem - (long long)binAbove);
    }
}

// ---------------------------------------------------------------------------
// Fix-up: scatter the kept window elements; collect exact ties.
__global__ void k_fix(float* __restrict__ out) {
    unsigned n = g_nList; if (n > LIST_CAP) n = LIST_CAP;
    unsigned T = g_T;
    int tid = blockIdx.x * blockDim.x + threadIdx.x;
    int stride = gridDim.x * blockDim.x;
    for (unsigned j = tid; j < n; j += stride) {
        uint2 e = g_list[j];
        unsigned b = e.y & 0x7FFFFFFFu;
        if (b > T) {
            out[e.x] = __uint_as_float(e.y);
        } else if (b == T) {
            unsigned p = atomicAdd(&g_eqCount, 1u);
            if (p < EQ_CAP) { g_eqIdx[p] = e.x; g_eqVal[p] = e.y; }
        }
    }
}

// ---------------------------------------------------------------------------
// Ties at exactly T: keep the `need` smallest flat indices (lax.top_k order).
__global__ void k_tie(float* __restrict__ out) {
    unsigned int cnt = g_eqCount;
    if (cnt > EQ_CAP) cnt = EQ_CAP;
    unsigned int need = g_need;
    if (need == 0 || cnt == 0) return;
    if (need >= cnt) {
        for (unsigned i = threadIdx.x; i < cnt; i += blockDim.x)
            out[g_eqIdx[i]] = __uint_as_float(g_eqVal[i]);
        return;
    }
    for (unsigned i = threadIdx.x; i < cnt; i += blockDim.x) {
        unsigned idx = g_eqIdx[i];
        unsigned r = 0;
        for (unsigned j = 0; j < cnt; j++) r += (g_eqIdx[j] < idx) ? 1u : 0u;
        if (r < need) out[idx] = __uint_as_float(g_eqVal[i]);
    }
}

// ---------------------------------------------------------------------------
extern "C" void kernel_launch(void* const* d_in, const int* in_sizes, int n_in,
                              void* d_out, int out_size) {
    const float* x = (const float*)d_in[0];
    float* out = (float*)d_out;

    k_zero<<<256, 256>>>();
    k_sample<<<128, 256>>>((const float4*)x);
    k_sscan<<<1, 1024>>>();
    k_main<<<GRID_MAIN, BLK_MAIN>>>((const float4*)x, (float4*)out);
    k_hist<<<256, 256>>>();
    k_wreduce<<<NCHUNKS, 256>>>();
    k_wscan<<<1, 1024>>>();
    k_fix<<<256, 256>>>(out);
    k_tie<<<1, 256>>>(out);
}